// round 11
// baseline (speedup 1.0000x reference)
#include <cuda_runtime.h>
#include <cstdint>

// out[b,m] = einsum('bd,cd,ce,em->bm', bp, mp, CE, W)
//   K0 : CEh[e][c] = fp16(CE[c][e])
//   G1 : A1[q][d,e] = sum_{c in quarter q} mp[c,d]*CE[c,e]  (fp16 mma, fp32 acc,
//        5-stage cp.async pipeline, wait->sync->load order, warp tile 32d x 64e)
//   G2 : part[p][b,e] = bp[:,p 64-col slab] @ (sum_q A1[q])[slab,:]  (256 blocks)
//   G3a: Z2[chunk] = partial sums (16 chunks x 16)   G3b: out = Z @ W
// B=128, C=16384, E=64, M=128 fp32.

#define C_DIM 16384
#define E_DIM 64
#define B_DIM 128
#define M_DIM 128

#define KSPLIT 4
#define KQ     (C_DIM / KSPLIT)   // 4096
#define KC     16
#define KITERS (KQ / KC)          // 256
#define DT     256                // d-tile per CTA

#define AST    260                // A smem row stride in floats (256 + 4), bank-safe
#define A_ROW_B (AST * 4)         // 1040 bytes
#define A_STG_F (KC * AST)
#define A_STG_B (KC * A_ROW_B)    // 16640 bytes
#define BSTH   24                 // B smem row stride in fp16 (16 + 8)
#define B_STG_B (E_DIM * BSTH * 2)  // 3072 bytes
#define NSTG   5
#define B_OFF_B (NSTG * A_STG_B)
#define SMEM_BYTES (B_OFF_B + NSTG * B_STG_B)   // 98560 -> 2 CTAs/SM

#define CH ((size_t)C_DIM * E_DIM)
#define NPART 256

__device__ float    g_A1  [KSPLIT * CH];                   // 16 MB
__device__ uint16_t g_CEh [CH];                            // 2 MB fp16, [e][c]
__device__ float    g_part[(size_t)NPART * B_DIM * E_DIM]; // 8 MB
__device__ float    g_Z2  [16 * (size_t)B_DIM * E_DIM];

// ---------------- helpers ----------------
__device__ __forceinline__ uint32_t smem_u32(const void* p) {
    uint32_t a;
    asm("{ .reg .u64 t; cvta.to.shared.u64 t, %1; cvt.u32.u64 %0, t; }" : "=r"(a) : "l"(p));
    return a;
}
__device__ __forceinline__ void cp16(uint32_t s, const void* g) {
    asm volatile("cp.async.cg.shared.global [%0], [%1], 16;" :: "r"(s), "l"(g) : "memory");
}
#define CP_COMMIT() asm volatile("cp.async.commit_group;" ::: "memory")
#define CP_WAIT3()  asm volatile("cp.async.wait_group 3;" ::: "memory")

__device__ __forceinline__ uint32_t pk16(float lo, float hi) {
    uint32_t r;
    asm("cvt.rn.f16x2.f32 %0, %1, %2;" : "=r"(r) : "f"(hi), "f"(lo));
    return r;
}
__device__ __forceinline__ void mma_f16(float* c, const uint32_t* a, const uint32_t* b) {
    asm volatile(
        "mma.sync.aligned.m16n8k16.row.col.f32.f16.f16.f32 "
        "{%0,%1,%2,%3}, {%4,%5,%6,%7}, {%8,%9}, {%0,%1,%2,%3};"
        : "+f"(c[0]), "+f"(c[1]), "+f"(c[2]), "+f"(c[3])
        : "r"(a[0]), "r"(a[1]), "r"(a[2]), "r"(a[3]), "r"(b[0]), "r"(b[1]));
}

// ---------------- K0: CEh[e][c] = fp16(CE[c][e]) ----------------
__global__ void __launch_bounds__(256) k0_cvt(const float* __restrict__ ce) {
    int idx = blockIdx.x * 256 + threadIdx.x;
    int e  = idx >> 11;
    int c0 = (idx & 2047) << 3;
    uint32_t r[4];
#pragma unroll
    for (int j = 0; j < 4; j++) {
        float v0 = __ldg(ce + (size_t)(c0 + 2*j)     * E_DIM + e);
        float v1 = __ldg(ce + (size_t)(c0 + 2*j + 1) * E_DIM + e);
        r[j] = pk16(v0, v1);
    }
    *reinterpret_cast<uint4*>(g_CEh + (size_t)e * C_DIM + c0) =
        make_uint4(r[0], r[1], r[2], r[3]);
}

// ---------------- G1 ----------------
// CTA tile 256(d) x 64(e). 8 warps; warp wid owns d rows [wid*32, wid*32+32).
__device__ __forceinline__ void g1_load(uint32_t sbase, int stage, size_t krow, int tid,
                                        const float* __restrict__ mp, size_t D0) {
    uint32_t sA = sbase + (uint32_t)(stage * A_STG_B);
    uint32_t sB = sbase + (uint32_t)(B_OFF_B + stage * B_STG_B);
#pragma unroll
    for (int i = 0; i < 4; i++) {                 // A: 16 k-rows x 1024 B (fp32)
        int q = tid + 256 * i;                    // 0..1023
        int row = q >> 6, c16 = q & 63;
        cp16(sA + (uint32_t)(row * A_ROW_B + c16 * 16),
             mp + (krow + (size_t)row) * C_DIM + D0 + (size_t)c16 * 4);
    }
    if (tid < 128) {                              // B: 64 e-rows x 32 B (fp16)
        int e = tid >> 1, h = tid & 1;
        cp16(sB + (uint32_t)(e * (BSTH * 2) + h * 16),
             g_CEh + (size_t)e * C_DIM + krow + (size_t)h * 8);
    }
}

__global__ void __launch_bounds__(256, 2)
g1_mpce(const float* __restrict__ mp) {
    extern __shared__ float sm[];
    uint32_t sbase = smem_u32(sm);
    const int tid  = threadIdx.x;
    const int wid  = tid >> 5, lane = tid & 31;
    const int lq   = lane & 3, lr = lane >> 2;
    const int wd   = wid * 32;
    const int slab = blockIdx.x & 63;
    const int kh   = blockIdx.x >> 6;     // 0..3
    const size_t D0 = (size_t)slab * DT;
    const size_t K0 = (size_t)kh * KQ;

    float acc[2][8][4];
#pragma unroll
    for (int mf = 0; mf < 2; mf++)
#pragma unroll
        for (int nf = 0; nf < 8; nf++)
#pragma unroll
            for (int j = 0; j < 4; j++) acc[mf][nf][j] = 0.f;

    // prologue: stages 0..3 in flight (4 groups)
#pragma unroll
    for (int s = 0; s < 4; s++) {
        g1_load(sbase, s, K0 + (size_t)s * KC, tid, mp, D0);
        CP_COMMIT();
    }

    int stage = 0;
    for (int k = 0; k < KITERS; k++) {
        CP_WAIT3();            // own group k done (3 newer may remain)
        __syncthreads();       // publish all threads' group-k data
        if (k + 4 < KITERS) {  // overwrite stage (k-1)%5: consumed in iter k-1
            int ns = stage + 4; if (ns >= NSTG) ns -= NSTG;
            g1_load(sbase, ns, K0 + (size_t)(k + 4) * KC, tid, mp, D0);
        }
        CP_COMMIT();           // empty in tail keeps wait_group accounting exact

        const float*    Af = sm + stage * A_STG_F;
        const uint16_t* Bh = reinterpret_cast<const uint16_t*>(
            reinterpret_cast<const char*>(sm) + B_OFF_B + stage * B_STG_B);

        const float* Ak0 = Af + (2 * lq) * AST;       // k = 2lq
        const float* Ak1 = Ak0 + AST;                 // k = 2lq+1
        const float* Ak8 = Ak0 + 8 * AST;             // k = 2lq+8
        const float* Ak9 = Ak8 + AST;                 // k = 2lq+9

        uint32_t au[2][4];
#pragma unroll
        for (int mf = 0; mf < 2; mf++) {
            int dw = wd + mf * 16 + lr;
            au[mf][0] = pk16(Ak0[dw],     Ak1[dw]);
            au[mf][1] = pk16(Ak0[dw + 8], Ak1[dw + 8]);
            au[mf][2] = pk16(Ak8[dw],     Ak9[dw]);
            au[mf][3] = pk16(Ak8[dw + 8], Ak9[dw + 8]);
        }
        uint32_t bu[8][2];
#pragma unroll
        for (int nf = 0; nf < 8; nf++) {
            int ew = nf * 8 + lr;
            bu[nf][0] = *reinterpret_cast<const uint32_t*>(Bh + ew * BSTH + 2 * lq);
            bu[nf][1] = *reinterpret_cast<const uint32_t*>(Bh + ew * BSTH + 2 * lq + 8);
        }
#pragma unroll
        for (int mf = 0; mf < 2; mf++)
#pragma unroll
            for (int nf = 0; nf < 8; nf++)
                mma_f16(acc[mf][nf], au[mf], bu[nf]);

        stage = (stage + 1 == NSTG) ? 0 : stage + 1;
    }

    float* ob = g_A1 + (size_t)kh * CH;
#pragma unroll
    for (int mf = 0; mf < 2; mf++) {
        size_t r0 = D0 + (size_t)(wd + mf * 16 + lr);
#pragma unroll
        for (int nf = 0; nf < 8; nf++) {
            int e0 = nf * 8 + 2 * lq;
            *reinterpret_cast<float2*>(&ob[r0 * E_DIM + e0]) =
                make_float2(acc[mf][nf][0], acc[mf][nf][1]);
            *reinterpret_cast<float2*>(&ob[(r0 + 8) * E_DIM + e0]) =
                make_float2(acc[mf][nf][2], acc[mf][nf][3]);
        }
    }
}

// ---------------- G2: 256 blocks, each 64 c-columns ----------------
__global__ void __launch_bounds__(256)
g2_bpA1(const float* __restrict__ bp) {
    __shared__ float bps[128 * 36];
    __shared__ float a1s[32 * 68];
    int tid = threadIdx.x;
    int tx = tid & 15, ty = tid >> 4;
    size_t cbase = (size_t)blockIdx.x * 64;

    float acc[8][4];
#pragma unroll
    for (int i = 0; i < 8; i++)
#pragma unroll
        for (int j = 0; j < 4; j++) acc[i][j] = 0.f;

    for (int cc = 0; cc < 2; cc++) {
        size_t c0 = cbase + (size_t)cc * 32;
#pragma unroll
        for (int i = 0; i < 4; i++) {
            int q = tid + 256 * i;
            int row = q >> 3, c4 = q & 7;
            *reinterpret_cast<float4*>(&bps[row * 36 + c4 * 4]) =
                *reinterpret_cast<const float4*>(&bp[(size_t)row * C_DIM + c0 + c4 * 4]);
        }
#pragma unroll
        for (int i = 0; i < 2; i++) {
            int q = tid + 256 * i;
            int row = q >> 4, c4 = q & 15;
            size_t gi = (c0 + (size_t)row) * E_DIM + c4 * 4;
            float4 v0 = *reinterpret_cast<const float4*>(&g_A1[gi]);
            float4 v1 = *reinterpret_cast<const float4*>(&g_A1[CH + gi]);
            float4 v2 = *reinterpret_cast<const float4*>(&g_A1[2 * CH + gi]);
            float4 v3 = *reinterpret_cast<const float4*>(&g_A1[3 * CH + gi]);
            *reinterpret_cast<float4*>(&a1s[row * 68 + c4 * 4]) =
                make_float4((v0.x + v1.x) + (v2.x + v3.x),
                            (v0.y + v1.y) + (v2.y + v3.y),
                            (v0.z + v1.z) + (v2.z + v3.z),
                            (v0.w + v1.w) + (v2.w + v3.w));
        }
        __syncthreads();
#pragma unroll 4
        for (int c = 0; c < 32; c++) {
            float4 bv = *reinterpret_cast<const float4*>(&a1s[c * 68 + tx * 4]);
#pragma unroll
            for (int i = 0; i < 8; i++) {
                float a = bps[(ty * 8 + i) * 36 + c];
                acc[i][0] += a * bv.x; acc[i][1] += a * bv.y;
                acc[i][2] += a * bv.z; acc[i][3] += a * bv.w;
            }
        }
        __syncthreads();
    }
    float* op = g_part + (size_t)blockIdx.x * (B_DIM * E_DIM);
#pragma unroll
    for (int i = 0; i < 8; i++)
        *reinterpret_cast<float4*>(&op[(ty * 8 + i) * E_DIM + tx * 4]) =
            make_float4(acc[i][0], acc[i][1], acc[i][2], acc[i][3]);
}

// ---------------- G3a: coalesced chunked reduce (16 chunks x 16 partials) ----------------
__global__ void __launch_bounds__(256)
g3a_reduce() {
    int chunk = blockIdx.x >> 5;                           // 0..15
    int be = ((blockIdx.x & 31) << 8) + threadIdx.x;       // 0..8191
    const float* p = g_part + (size_t)chunk * 16 * (B_DIM * E_DIM) + be;
    float s = 0.f;
#pragma unroll 8
    for (int i = 0; i < 16; i++)
        s += p[(size_t)i * (B_DIM * E_DIM)];
    g_Z2[(size_t)chunk * (B_DIM * E_DIM) + be] = s;
}

// ---------------- G3b: out = Z @ W ----------------
__global__ void __launch_bounds__(128)
g3b_out(const float* __restrict__ w, float* __restrict__ out) {
    __shared__ float zs[E_DIM];
    int b = blockIdx.x, t = threadIdx.x;
    if (t < E_DIM) {
        int be = b * E_DIM + t;
        float s = 0.f;
#pragma unroll
        for (int ch = 0; ch < 16; ch++)
            s += g_Z2[(size_t)ch * (B_DIM * E_DIM) + be];
        zs[t] = s;
    }
    __syncthreads();
    float acc = 0.f;
#pragma unroll 8
    for (int e = 0; e < E_DIM; e++)
        acc += zs[e] * w[e * M_DIM + t];
    out[b * M_DIM + t] = acc;
}

// ---------------- launch ----------------
extern "C" void kernel_launch(void* const* d_in, const int* in_sizes, int n_in,
                              void* d_out, int out_size) {
    const float* bp = (const float*)d_in[0];
    const float* mp = (const float*)d_in[1];
    const float* ce = (const float*)d_in[2];
    const float* w  = (const float*)d_in[3];
    float* out = (float*)d_out;

    cudaFuncSetAttribute(g1_mpce, cudaFuncAttributeMaxDynamicSharedMemorySize, SMEM_BYTES);

    k0_cvt<<<512, 256>>>(ce);
    g1_mpce<<<64 * KSPLIT, 256, SMEM_BYTES>>>(mp);
    g2_bpA1<<<NPART, 256>>>(bp);
    g3a_reduce<<<512, 256>>>();
    g3b_out<<<B_DIM, M_DIM>>>(w, out);
}

// round 12
// speedup vs baseline: 1.0555x; 1.0555x over previous
#include <cuda_runtime.h>
#include <cstdint>

// out[b,m] = einsum('bd,cd,ce,em->bm', bp, mp, CE, W)
//   K0 : CEh[e][c] = fp16(CE[c][e])
//   G1 : A1[q][d,e] = sum_{c in quarter q} mp[c,d]*CE[c,e]  (fp16 mma, fp32 acc,
//        4-stage cp.async pipeline, warp tile 32d x 64e, B frags via ldmatrix)
//   G2 : part[p][b,e] = bp[:,p 64-col slab] @ (sum_q A1[q])[slab,:]  (256 blocks)
//   G3a: Z2[chunk] = partial sums (16 chunks x 16)   G3b: out = Z @ W
// B=128, C=16384, E=64, M=128 fp32.

#define C_DIM 16384
#define E_DIM 64
#define B_DIM 128
#define M_DIM 128

#define KSPLIT 4
#define KQ     (C_DIM / KSPLIT)   // 4096
#define KC     16
#define KITERS (KQ / KC)          // 256
#define DT     256                // d-tile per CTA

#define AST    260                // A smem row stride in floats (256 + 4), bank-safe
#define A_ROW_B (AST * 4)         // 1040 bytes
#define A_STG_F (KC * AST)
#define A_STG_B (KC * A_ROW_B)    // 16640 bytes
#define BSTH   24                 // B smem row stride in fp16 (16 + 8)
#define B_STG_B (E_DIM * BSTH * 2)  // 3072 bytes
#define NSTG   4
#define B_OFF_B (NSTG * A_STG_B)
#define SMEM_BYTES (B_OFF_B + NSTG * B_STG_B)   // 78848 -> 2 CTAs/SM

#define CH ((size_t)C_DIM * E_DIM)
#define NPART 256

__device__ float    g_A1  [KSPLIT * CH];                   // 16 MB
__device__ uint16_t g_CEh [CH];                            // 2 MB fp16, [e][c]
__device__ float    g_part[(size_t)NPART * B_DIM * E_DIM]; // 8 MB
__device__ float    g_Z2  [16 * (size_t)B_DIM * E_DIM];

// ---------------- helpers ----------------
__device__ __forceinline__ uint32_t smem_u32(const void* p) {
    uint32_t a;
    asm("{ .reg .u64 t; cvta.to.shared.u64 t, %1; cvt.u32.u64 %0, t; }" : "=r"(a) : "l"(p));
    return a;
}
__device__ __forceinline__ void cp16(uint32_t s, const void* g) {
    asm volatile("cp.async.cg.shared.global [%0], [%1], 16;" :: "r"(s), "l"(g) : "memory");
}
#define CP_COMMIT() asm volatile("cp.async.commit_group;" ::: "memory")
#define CP_WAIT2()  asm volatile("cp.async.wait_group 2;" ::: "memory")

__device__ __forceinline__ uint32_t pk16(float lo, float hi) {
    uint32_t r;
    asm("cvt.rn.f16x2.f32 %0, %1, %2;" : "=r"(r) : "f"(hi), "f"(lo));
    return r;
}
__device__ __forceinline__ void mma_f16(float* c, const uint32_t* a, const uint32_t* b) {
    asm volatile(
        "mma.sync.aligned.m16n8k16.row.col.f32.f16.f16.f32 "
        "{%0,%1,%2,%3}, {%4,%5,%6,%7}, {%8,%9}, {%0,%1,%2,%3};"
        : "+f"(c[0]), "+f"(c[1]), "+f"(c[2]), "+f"(c[3])
        : "r"(a[0]), "r"(a[1]), "r"(a[2]), "r"(a[3]), "r"(b[0]), "r"(b[1]));
}

// ---------------- K0: CEh[e][c] = fp16(CE[c][e]) ----------------
__global__ void __launch_bounds__(256) k0_cvt(const float* __restrict__ ce) {
    int idx = blockIdx.x * 256 + threadIdx.x;
    int e  = idx >> 11;
    int c0 = (idx & 2047) << 3;
    uint32_t r[4];
#pragma unroll
    for (int j = 0; j < 4; j++) {
        float v0 = __ldg(ce + (size_t)(c0 + 2*j)     * E_DIM + e);
        float v1 = __ldg(ce + (size_t)(c0 + 2*j + 1) * E_DIM + e);
        r[j] = pk16(v0, v1);
    }
    *reinterpret_cast<uint4*>(g_CEh + (size_t)e * C_DIM + c0) =
        make_uint4(r[0], r[1], r[2], r[3]);
}

// ---------------- G1 ----------------
// CTA tile 256(d) x 64(e). 8 warps; warp wid owns d rows [wid*32, wid*32+32).
__device__ __forceinline__ void g1_load(uint32_t sbase, int stage, size_t krow, int tid,
                                        const float* __restrict__ mp, size_t D0) {
    uint32_t sA = sbase + (uint32_t)(stage * A_STG_B);
    uint32_t sB = sbase + (uint32_t)(B_OFF_B + stage * B_STG_B);
#pragma unroll
    for (int i = 0; i < 4; i++) {                 // A: 16 k-rows x 1024 B (fp32)
        int q = tid + 256 * i;                    // 0..1023
        int row = q >> 6, c16 = q & 63;
        cp16(sA + (uint32_t)(row * A_ROW_B + c16 * 16),
             mp + (krow + (size_t)row) * C_DIM + D0 + (size_t)c16 * 4);
    }
    if (tid < 128) {                              // B: 64 e-rows x 32 B (fp16)
        int e = tid >> 1, h = tid & 1;
        cp16(sB + (uint32_t)(e * (BSTH * 2) + h * 16),
             g_CEh + (size_t)e * C_DIM + krow + (size_t)h * 8);
    }
}

__global__ void __launch_bounds__(256, 2)
g1_mpce(const float* __restrict__ mp) {
    extern __shared__ float sm[];
    uint32_t sbase = smem_u32(sm);
    const int tid  = threadIdx.x;
    const int wid  = tid >> 5, lane = tid & 31;
    const int lq   = lane & 3, lr = lane >> 2;
    const int wd   = wid * 32;
    const int slab = blockIdx.x & 63;
    const int kh   = blockIdx.x >> 6;     // 0..3
    const size_t D0 = (size_t)slab * DT;
    const size_t K0 = (size_t)kh * KQ;

    // ldmatrix per-lane offset (bytes) within a B stage:
    // group g = lane>>3 -> (g>>1) selects nf parity row-block, (g&1) selects k-half 8..15
    const int lg = lane >> 3, lrow = lane & 7;
    const uint32_t ldm_off =
        (uint32_t)(((((lg >> 1) * 8) + lrow) * BSTH + (lg & 1) * 8) * 2);

    float acc[2][8][4];
#pragma unroll
    for (int mf = 0; mf < 2; mf++)
#pragma unroll
        for (int nf = 0; nf < 8; nf++)
#pragma unroll
            for (int j = 0; j < 4; j++) acc[mf][nf][j] = 0.f;

    g1_load(sbase, 0, K0,          tid, mp, D0); CP_COMMIT();
    g1_load(sbase, 1, K0 + KC,     tid, mp, D0); CP_COMMIT();
    g1_load(sbase, 2, K0 + 2 * KC, tid, mp, D0); CP_COMMIT();

    int stage = 0;
    for (int k = 0; k < KITERS; k++) {
        CP_WAIT2();            // own group k done
        __syncthreads();       // publish all threads' group-k data
        if (k + 3 < KITERS) {
            int ns = stage + 3; if (ns >= NSTG) ns -= NSTG;
            g1_load(sbase, ns, K0 + (size_t)(k + 3) * KC, tid, mp, D0);
        }
        CP_COMMIT();

        const float* Af = sm + stage * A_STG_F;

        const float* Ak0 = Af + (2 * lq) * AST;       // k = 2lq
        const float* Ak1 = Ak0 + AST;                 // k = 2lq+1
        const float* Ak8 = Ak0 + 8 * AST;             // k = 2lq+8
        const float* Ak9 = Ak8 + AST;                 // k = 2lq+9

        uint32_t au[2][4];
#pragma unroll
        for (int mf = 0; mf < 2; mf++) {
            int dw = wd + mf * 16 + lr;
            au[mf][0] = pk16(Ak0[dw],     Ak1[dw]);
            au[mf][1] = pk16(Ak0[dw + 8], Ak1[dw + 8]);
            au[mf][2] = pk16(Ak8[dw],     Ak9[dw]);
            au[mf][3] = pk16(Ak8[dw + 8], Ak9[dw + 8]);
        }

        // B fragments via ldmatrix.x4: each covers 2 nf tiles (b0,b1 each)
        uint32_t bu[8][2];
        uint32_t baddr = sbase + (uint32_t)(B_OFF_B + stage * B_STG_B) + ldm_off;
#pragma unroll
        for (int p = 0; p < 4; p++) {
            asm volatile(
                "ldmatrix.sync.aligned.m8n8.x4.shared.b16 {%0,%1,%2,%3}, [%4];"
                : "=r"(bu[2*p][0]), "=r"(bu[2*p][1]),
                  "=r"(bu[2*p+1][0]), "=r"(bu[2*p+1][1])
                : "r"(baddr + (uint32_t)(p * 16 * BSTH * 2)));
        }

#pragma unroll
        for (int mf = 0; mf < 2; mf++)
#pragma unroll
            for (int nf = 0; nf < 8; nf++)
                mma_f16(acc[mf][nf], au[mf], bu[nf]);

        stage = (stage + 1 == NSTG) ? 0 : stage + 1;
    }

    float* ob = g_A1 + (size_t)kh * CH;
#pragma unroll
    for (int mf = 0; mf < 2; mf++) {
        size_t r0 = D0 + (size_t)(wd + mf * 16 + lr);
#pragma unroll
        for (int nf = 0; nf < 8; nf++) {
            int e0 = nf * 8 + 2 * lq;
            *reinterpret_cast<float2*>(&ob[r0 * E_DIM + e0]) =
                make_float2(acc[mf][nf][0], acc[mf][nf][1]);
            *reinterpret_cast<float2*>(&ob[(r0 + 8) * E_DIM + e0]) =
                make_float2(acc[mf][nf][2], acc[mf][nf][3]);
        }
    }
}

// ---------------- G2: 256 blocks, each 64 c-columns ----------------
__global__ void __launch_bounds__(256)
g2_bpA1(const float* __restrict__ bp) {
    __shared__ float bps[128 * 36];
    __shared__ float a1s[32 * 68];
    int tid = threadIdx.x;
    int tx = tid & 15, ty = tid >> 4;
    size_t cbase = (size_t)blockIdx.x * 64;

    float acc[8][4];
#pragma unroll
    for (int i = 0; i < 8; i++)
#pragma unroll
        for (int j = 0; j < 4; j++) acc[i][j] = 0.f;

    for (int cc = 0; cc < 2; cc++) {
        size_t c0 = cbase + (size_t)cc * 32;
#pragma unroll
        for (int i = 0; i < 4; i++) {
            int q = tid + 256 * i;
            int row = q >> 3, c4 = q & 7;
            *reinterpret_cast<float4*>(&bps[row * 36 + c4 * 4]) =
                *reinterpret_cast<const float4*>(&bp[(size_t)row * C_DIM + c0 + c4 * 4]);
        }
#pragma unroll
        for (int i = 0; i < 2; i++) {
            int q = tid + 256 * i;
            int row = q >> 4, c4 = q & 15;
            size_t gi = (c0 + (size_t)row) * E_DIM + c4 * 4;
            float4 v0 = *reinterpret_cast<const float4*>(&g_A1[gi]);
            float4 v1 = *reinterpret_cast<const float4*>(&g_A1[CH + gi]);
            float4 v2 = *reinterpret_cast<const float4*>(&g_A1[2 * CH + gi]);
            float4 v3 = *reinterpret_cast<const float4*>(&g_A1[3 * CH + gi]);
            *reinterpret_cast<float4*>(&a1s[row * 68 + c4 * 4]) =
                make_float4((v0.x + v1.x) + (v2.x + v3.x),
                            (v0.y + v1.y) + (v2.y + v3.y),
                            (v0.z + v1.z) + (v2.z + v3.z),
                            (v0.w + v1.w) + (v2.w + v3.w));
        }
        __syncthreads();
#pragma unroll 4
        for (int c = 0; c < 32; c++) {
            float4 bv = *reinterpret_cast<const float4*>(&a1s[c * 68 + tx * 4]);
#pragma unroll
            for (int i = 0; i < 8; i++) {
                float a = bps[(ty * 8 + i) * 36 + c];
                acc[i][0] += a * bv.x; acc[i][1] += a * bv.y;
                acc[i][2] += a * bv.z; acc[i][3] += a * bv.w;
            }
        }
        __syncthreads();
    }
    float* op = g_part + (size_t)blockIdx.x * (B_DIM * E_DIM);
#pragma unroll
    for (int i = 0; i < 8; i++)
        *reinterpret_cast<float4*>(&op[(ty * 8 + i) * E_DIM + tx * 4]) =
            make_float4(acc[i][0], acc[i][1], acc[i][2], acc[i][3]);
}

// ---------------- G3a: coalesced chunked reduce (16 chunks x 16 partials) ----------------
__global__ void __launch_bounds__(256)
g3a_reduce() {
    int chunk = blockIdx.x >> 5;                           // 0..15
    int be = ((blockIdx.x & 31) << 8) + threadIdx.x;       // 0..8191
    const float* p = g_part + (size_t)chunk * 16 * (B_DIM * E_DIM) + be;
    float s = 0.f;
#pragma unroll 8
    for (int i = 0; i < 16; i++)
        s += p[(size_t)i * (B_DIM * E_DIM)];
    g_Z2[(size_t)chunk * (B_DIM * E_DIM) + be] = s;
}

// ---------------- G3b: out = Z @ W ----------------
__global__ void __launch_bounds__(128)
g3b_out(const float* __restrict__ w, float* __restrict__ out) {
    __shared__ float zs[E_DIM];
    int b = blockIdx.x, t = threadIdx.x;
    if (t < E_DIM) {
        int be = b * E_DIM + t;
        float s = 0.f;
#pragma unroll
        for (int ch = 0; ch < 16; ch++)
            s += g_Z2[(size_t)ch * (B_DIM * E_DIM) + be];
        zs[t] = s;
    }
    __syncthreads();
    float acc = 0.f;
#pragma unroll 8
    for (int e = 0; e < E_DIM; e++)
        acc += zs[e] * w[e * M_DIM + t];
    out[b * M_DIM + t] = acc;
}

// ---------------- launch ----------------
extern "C" void kernel_launch(void* const* d_in, const int* in_sizes, int n_in,
                              void* d_out, int out_size) {
    const float* bp = (const float*)d_in[0];
    const float* mp = (const float*)d_in[1];
    const float* ce = (const float*)d_in[2];
    const float* w  = (const float*)d_in[3];
    float* out = (float*)d_out;

    cudaFuncSetAttribute(g1_mpce, cudaFuncAttributeMaxDynamicSharedMemorySize, SMEM_BYTES);

    k0_cvt<<<512, 256>>>(ce);
    g1_mpce<<<64 * KSPLIT, 256, SMEM_BYTES>>>(mp);
    g2_bpA1<<<NPART, 256>>>(bp);
    g3a_reduce<<<512, 256>>>();
    g3b_out<<<B_DIM, M_DIM>>>(w, out);
}